// round 7
// baseline (speedup 1.0000x reference)
#include <cuda_runtime.h>
#include <cuda_bf16.h>

#define BATCH     2048
#define NCLASSES  50257
#define KPOS      20
#define TPB       128   // 16 CTAs/SM -> all 2048 row-CTAs resident in ONE wave

// Scratch (allocation-free requirement -> __device__ globals).
__device__ float        g_row_loss[BATCH];
__device__ unsigned int g_done = 0;

__device__ __forceinline__ float softplus_f(float x) {
    // log(1+exp(x)) = max(x,0) + log(1+exp(-|x|)); exp arg <= 0 -> value in (0,1]
    return fmaxf(x, 0.0f) + __logf(1.0f + __expf(-fabsf(x)));
}

// Accumulate max(x,0) linearly; fold log terms into products (factor in (1,2]).
// One __logf per <=16 factors (prod <= 2^16, fp32-safe).
#define PROC4(v)                                                        \
    do {                                                                \
        lin += fmaxf((v).x, 0.0f) + fmaxf((v).y, 0.0f)                  \
             + fmaxf((v).z, 0.0f) + fmaxf((v).w, 0.0f);                 \
        p0 *= (1.0f + __expf(-fabsf((v).x)))                            \
            * (1.0f + __expf(-fabsf((v).y)));                           \
        p1 *= (1.0f + __expf(-fabsf((v).z)))                            \
            * (1.0f + __expf(-fabsf((v).w)));                           \
    } while (0)

__global__ __launch_bounds__(TPB)
void mlsm_row_kernel(const float* __restrict__ inp, const int* __restrict__ tgt,
                     float* __restrict__ out) {
    const int row = blockIdx.x;
    const int tid = threadIdx.x;
    const float* __restrict__ rp = inp + (size_t)row * NCLASSES;

    __shared__ int   s_t[KPOS];
    __shared__ float s_warp[TPB / 32];
    __shared__ float s_total;
    __shared__ int   s_last;

    if (tid < KPOS) s_t[tid] = tgt[row * KPOS + tid];

    // Row base only 4B-aligned (NCLASSES odd): scalar prologue to 16B alignment.
    const int mis = (int)(((size_t)row * NCLASSES) & 3);
    const int pro = (4 - mis) & 3;

    float acc = 0.0f;
    if (tid < pro) acc += softplus_f(rp[tid]);

    const float4* __restrict__ vp = (const float4*)(rp + pro);
    const int nv = (NCLASSES - pro) >> 2;

    // Main loop: 4 front-batched LDG.128 (MLP=4), 16 elems per __logf.
    int i = tid;
    for (; i + 3 * TPB < nv; i += 4 * TPB) {
        float4 a = vp[i];
        float4 b = vp[i + TPB];
        float4 c = vp[i + 2 * TPB];
        float4 d = vp[i + 3 * TPB];
        float lin = 0.0f, p0 = 1.0f, p1 = 1.0f;
        PROC4(a); PROC4(b); PROC4(c); PROC4(d);
        acc += lin + __logf(p0 * p1);
    }
    for (; i < nv; i += TPB) {
        float4 a = vp[i];
        float lin = 0.0f, p0 = 1.0f, p1 = 1.0f;
        PROC4(a);
        acc += lin + __logf(p0 * p1);
    }
    const int base = pro + (nv << 2);
    for (int j = base + tid; j < NCLASSES; j += TPB)
        acc += softplus_f(rp[j]);

    // Block reduce -> s_total (sum of softplus over the row).
    const int lane = tid & 31;
    const int wid  = tid >> 5;
    #pragma unroll
    for (int o = 16; o > 0; o >>= 1)
        acc += __shfl_down_sync(0xFFFFFFFFu, acc, o);
    if (lane == 0) s_warp[wid] = acc;
    __syncthreads();
    if (wid == 0) {
        float v = (lane < TPB / 32) ? s_warp[lane] : 0.0f;
        #pragma unroll
        for (int o = 16; o > 0; o >>= 1)
            v += __shfl_down_sync(0xFFFFFFFFu, v, o);
        if (lane == 0) s_total = v;
    }
    __syncthreads();

    // Warp 0: K=20 label handling -> row loss.
    if (wid == 0) {
        float pos = 0.0f, corr = 0.0f;
        int   nfirst = 0;
        if (lane < KPOS) {
            const int t = s_t[lane];
            const float x = __ldg(rp + t);
            pos = -softplus_f(-x);                 // log_sigmoid, per occurrence
            bool first = true;
            #pragma unroll
            for (int j = 0; j < KPOS; ++j)
                if (j < lane && s_t[j] == t) first = false;
            if (first) { corr = softplus_f(x); nfirst = 1; }  // dedup'd
        }
        #pragma unroll
        for (int o = 16; o > 0; o >>= 1) {
            pos    += __shfl_down_sync(0xFFFFFFFFu, pos, o);
            corr   += __shfl_down_sync(0xFFFFFFFFu, corr, o);
            nfirst += __shfl_down_sync(0xFFFFFFFFu, nfirst, o);
        }
        if (lane == 0) {
            const float neg_mean = (corr - s_total) / (float)(NCLASSES - nfirst);
            g_row_loss[row] = pos / (float)KPOS + neg_mean;
        }
    }
    __syncthreads();   // order g_row_loss write before the fence below

    // Fused final reduce: last CTA sums all row losses (fixed order, deterministic)
    // and resets the counter so every graph replay starts clean.
    if (tid == 0) {
        __threadfence();
        unsigned int old = atomicAdd(&g_done, 1u);
        s_last = (old == BATCH - 1u) ? 1 : 0;
    }
    __syncthreads();
    if (s_last) {
        float a = 0.0f;
        for (int r = tid; r < BATCH; r += TPB)
            a += __ldcg(&g_row_loss[r]);           // bypass L1: cross-CTA data
        #pragma unroll
        for (int o = 16; o > 0; o >>= 1)
            a += __shfl_down_sync(0xFFFFFFFFu, a, o);
        if (lane == 0) s_warp[wid] = a;
        __syncthreads();
        if (wid == 0) {
            float v = (lane < TPB / 32) ? s_warp[lane] : 0.0f;
            #pragma unroll
            for (int o = 16; o > 0; o >>= 1)
                v += __shfl_down_sync(0xFFFFFFFFu, v, o);
            if (lane == 0) {
                out[0] = -v / (float)BATCH;
                g_done = 0;                        // reset for next replay
            }
        }
    }
}

extern "C" void kernel_launch(void* const* d_in, const int* in_sizes, int n_in,
                              void* d_out, int out_size) {
    const float* inp = (const float*)d_in[0];
    const int*   tgt = (const int*)d_in[1];
    if (n_in >= 2 && in_sizes[0] == BATCH * KPOS && in_sizes[1] == BATCH * NCLASSES) {
        inp = (const float*)d_in[1];
        tgt = (const int*)d_in[0];
    }
    mlsm_row_kernel<<<BATCH, TPB>>>(inp, tgt, (float*)d_out);
}

// round 8
// speedup vs baseline: 1.0786x; 1.0786x over previous
#include <cuda_runtime.h>
#include <cuda_bf16.h>

#define BATCH     2048
#define NCLASSES  50257
#define HALF      25128          // even split point (multiple of 4)
#define KPOS      20
#define TPB       256

// Scratch (allocation-free -> __device__ globals). Finalizers reset per-row
// state after use so every graph replay starts from zeros.
__device__ float        g_row_sum[BATCH];     // 2 atomicAdd contributions (commutative -> deterministic)
__device__ unsigned int g_row_cnt[BATCH];
__device__ float        g_pos[BATCH];
__device__ float        g_corr[BATCH];
__device__ int          g_nfirst[BATCH];
__device__ float        g_row_loss[BATCH];
__device__ unsigned int g_done = 0;

__device__ __forceinline__ float softplus_f(float x) {
    // log(1+exp(x)) = max(x,0) + log(1+exp(-|x|)); exp arg <= 0 -> value in (0,1]
    return fmaxf(x, 0.0f) + __logf(1.0f + __expf(-fabsf(x)));
}

// Accumulate max(x,0) linearly; fold log terms into products (factor in (1,2]).
// One __logf per <=16 factors (prod <= 2^16, fp32-safe).
#define PROC4(v)                                                        \
    do {                                                                \
        lin += fmaxf((v).x, 0.0f) + fmaxf((v).y, 0.0f)                  \
             + fmaxf((v).z, 0.0f) + fmaxf((v).w, 0.0f);                 \
        p0 *= (1.0f + __expf(-fabsf((v).x)))                            \
            * (1.0f + __expf(-fabsf((v).y)));                           \
        p1 *= (1.0f + __expf(-fabsf((v).z)))                            \
            * (1.0f + __expf(-fabsf((v).w)));                           \
    } while (0)

__global__ __launch_bounds__(TPB)
void mlsm_half_kernel(const float* __restrict__ inp, const int* __restrict__ tgt,
                      float* __restrict__ out) {
    const int bid  = blockIdx.x;
    const int row  = bid >> 1;
    const int half = bid & 1;
    const int tid  = threadIdx.x;
    const int lane = tid & 31;
    const int wid  = tid >> 5;

    const float* __restrict__ rp = inp + (size_t)row * NCLASSES;
    const int start = half ? HALF : 0;
    const int len   = half ? (NCLASSES - HALF) : HALF;
    const float* __restrict__ cp = rp + start;

    __shared__ int   s_t[KPOS];
    __shared__ float s_warp[TPB / 32];
    __shared__ int   s_last;

    if (half == 0 && tid < KPOS) s_t[tid] = tgt[row * KPOS + tid];

    // Chunk base only 4B-aligned (NCLASSES odd): scalar prologue to 16B.
    const int mis = (int)(((size_t)(row) * NCLASSES + start) & 3);
    const int pro = (4 - mis) & 3;

    float acc = 0.0f;
    if (tid < pro) acc += softplus_f(cp[tid]);

    const float4* __restrict__ vp = (const float4*)(cp + pro);
    const int nv = (len - pro) >> 2;

    // Main loop: 4 front-batched LDG.128 (MLP=4), 16 elems per __logf.
    int i = tid;
    for (; i + 3 * TPB < nv; i += 4 * TPB) {
        float4 a = vp[i];
        float4 b = vp[i + TPB];
        float4 c = vp[i + 2 * TPB];
        float4 d = vp[i + 3 * TPB];
        float lin = 0.0f, p0 = 1.0f, p1 = 1.0f;
        PROC4(a); PROC4(b); PROC4(c); PROC4(d);
        acc += lin + __logf(p0 * p1);
    }
    for (; i < nv; i += TPB) {
        float4 a = vp[i];
        float lin = 0.0f, p0 = 1.0f, p1 = 1.0f;
        PROC4(a);
        acc += lin + __logf(p0 * p1);
    }
    for (int j = pro + (nv << 2) + tid; j < len; j += TPB)
        acc += softplus_f(cp[j]);

    // Block reduce acc -> partial softplus sum for this half (in thread 0).
    #pragma unroll
    for (int o = 16; o > 0; o >>= 1)
        acc += __shfl_down_sync(0xFFFFFFFFu, acc, o);
    if (lane == 0) s_warp[wid] = acc;
    __syncthreads();
    if (wid == 0) {
        float v = (lane < TPB / 32) ? s_warp[lane] : 0.0f;
        #pragma unroll
        for (int o = 16; o > 0; o >>= 1)
            v += __shfl_down_sync(0xFFFFFFFFu, v, o);
        acc = v;   // thread 0 holds the half-sum
    }

    // Half-0 CTA: label terms (warp 0), published to globals by thread 0.
    if (half == 0 && wid == 0) {
        float pos = 0.0f, corr = 0.0f;
        int   nfirst = 0;
        if (lane < KPOS) {
            const int t = s_t[lane];
            const float x = __ldg(rp + t);
            pos = -softplus_f(-x);                 // log_sigmoid, per occurrence
            bool first = true;
            #pragma unroll
            for (int j = 0; j < KPOS; ++j)
                if (j < lane && s_t[j] == t) first = false;
            if (first) { corr = softplus_f(x); nfirst = 1; }  // dedup'd
        }
        #pragma unroll
        for (int o = 16; o > 0; o >>= 1) {
            pos    += __shfl_down_sync(0xFFFFFFFFu, pos, o);
            corr   += __shfl_down_sync(0xFFFFFFFFu, corr, o);
            nfirst += __shfl_down_sync(0xFFFFFFFFu, nfirst, o);
        }
        if (lane == 0) {
            g_pos[row]    = pos;
            g_corr[row]   = corr;
            g_nfirst[row] = nfirst;
        }
    }

    // Combine halves: 2 atomicAdds per row (commutative -> deterministic).
    // Second arrival finalizes the row; last finalizer reduces all rows.
    if (tid == 0) {
        s_last = 0;
        atomicAdd(&g_row_sum[row], acc);
        __threadfence();                            // sum + label stores visible
        unsigned int oldr = atomicAdd(&g_row_cnt[row], 1u);
        if (oldr == 1u) {                           // both halves done
            const float S    = __ldcg(&g_row_sum[row]);
            const float pos  = __ldcg(&g_pos[row]);
            const float corr = __ldcg(&g_corr[row]);
            const int   nf   = __ldcg(&g_nfirst[row]);
            g_row_loss[row] = pos / (float)KPOS
                            + (corr - S) / (float)(NCLASSES - nf);
            g_row_sum[row] = 0.0f;                  // reset for next replay
            g_row_cnt[row] = 0u;
            __threadfence();
            unsigned int oldg = atomicAdd(&g_done, 1u);
            if (oldg == BATCH - 1u) s_last = 1;
        }
    }
    __syncthreads();

    // Deterministic final reduce over the 2048 row losses in the last CTA.
    if (s_last) {
        float a = 0.0f;
        for (int r = tid; r < BATCH; r += TPB)
            a += __ldcg(&g_row_loss[r]);
        #pragma unroll
        for (int o = 16; o > 0; o >>= 1)
            a += __shfl_down_sync(0xFFFFFFFFu, a, o);
        if (lane == 0) s_warp[wid] = a;
        __syncthreads();
        if (wid == 0) {
            float v = (lane < TPB / 32) ? s_warp[lane] : 0.0f;
            #pragma unroll
            for (int o = 16; o > 0; o >>= 1)
                v += __shfl_down_sync(0xFFFFFFFFu, v, o);
            if (lane == 0) {
                out[0] = -v / (float)BATCH;
                g_done = 0;                         // reset for next replay
            }
        }
    }
}

extern "C" void kernel_launch(void* const* d_in, const int* in_sizes, int n_in,
                              void* d_out, int out_size) {
    const float* inp = (const float*)d_in[0];
    const int*   tgt = (const int*)d_in[1];
    if (n_in >= 2 && in_sizes[0] == BATCH * KPOS && in_sizes[1] == BATCH * NCLASSES) {
        inp = (const float*)d_in[1];
        tgt = (const int*)d_in[0];
    }
    mlsm_half_kernel<<<BATCH * 2, TPB>>>(inp, tgt, (float*)d_out);
}

// round 9
// speedup vs baseline: 1.0823x; 1.0034x over previous
#include <cuda_runtime.h>
#include <cuda_bf16.h>

#define BATCH     2048
#define NCLASSES  50257
#define HALF      25128          // even split point (multiple of 4)
#define KPOS      20
#define TPB       256

// Scratch (allocation-free -> __device__ globals). Finalizers reset per-row
// state after use so every graph replay starts from zeros.
__device__ float        g_row_sum[BATCH];     // 2 atomicAdd contributions (commutative -> deterministic)
__device__ unsigned int g_row_cnt[BATCH];
__device__ float        g_pos[BATCH];
__device__ float        g_corr[BATCH];
__device__ int          g_nfirst[BATCH];
__device__ float        g_row_loss[BATCH];
__device__ unsigned int g_done = 0;

__device__ __forceinline__ float softplus_f(float x) {
    // log(1+exp(x)) = max(x,0) + log(1+exp(-|x|)); exp arg <= 0 -> value in (0,1]
    return fmaxf(x, 0.0f) + __logf(1.0f + __expf(-fabsf(x)));
}

// Accumulate max(x,0) linearly; fold log terms into products (factor in (1,2]).
// One __logf per <=16 factors (prod <= 2^16, fp32-safe).
#define PROC4(v)                                                        \
    do {                                                                \
        lin += fmaxf((v).x, 0.0f) + fmaxf((v).y, 0.0f)                  \
             + fmaxf((v).z, 0.0f) + fmaxf((v).w, 0.0f);                 \
        p0 *= (1.0f + __expf(-fabsf((v).x)))                            \
            * (1.0f + __expf(-fabsf((v).y)));                           \
        p1 *= (1.0f + __expf(-fabsf((v).z)))                            \
            * (1.0f + __expf(-fabsf((v).w)));                           \
    } while (0)

__global__ __launch_bounds__(TPB)
void mlsm_half_kernel(const float* __restrict__ inp, const int* __restrict__ tgt,
                      float* __restrict__ out) {
    const int bid  = blockIdx.x;
    const int row  = bid >> 1;
    const int half = bid & 1;
    const int tid  = threadIdx.x;
    const int lane = tid & 31;
    const int wid  = tid >> 5;

    const float* __restrict__ rp = inp + (size_t)row * NCLASSES;
    const int start = half ? HALF : 0;
    const int len   = half ? (NCLASSES - HALF) : HALF;
    const float* __restrict__ cp = rp + start;

    __shared__ int   s_t[KPOS];
    __shared__ float s_warp[TPB / 32];
    __shared__ int   s_last;

    if (half == 0 && tid < KPOS) s_t[tid] = tgt[row * KPOS + tid];

    // Chunk base only 4B-aligned (NCLASSES odd): scalar prologue to 16B.
    const int mis = (int)(((size_t)(row) * NCLASSES + start) & 3);
    const int pro = (4 - mis) & 3;

    float acc = 0.0f;
    if (tid < pro) acc += softplus_f(cp[tid]);

    const float4* __restrict__ vp = (const float4*)(cp + pro);
    const int nv = (len - pro) >> 2;

    // Main loop: 4 front-batched LDG.128 (MLP=4), 16 elems per __logf.
    int i = tid;
    for (; i + 3 * TPB < nv; i += 4 * TPB) {
        float4 a = vp[i];
        float4 b = vp[i + TPB];
        float4 c = vp[i + 2 * TPB];
        float4 d = vp[i + 3 * TPB];
        float lin = 0.0f, p0 = 1.0f, p1 = 1.0f;
        PROC4(a); PROC4(b); PROC4(c); PROC4(d);
        acc += lin + __logf(p0 * p1);
    }
    for (; i < nv; i += TPB) {
        float4 a = vp[i];
        float lin = 0.0f, p0 = 1.0f, p1 = 1.0f;
        PROC4(a);
        acc += lin + __logf(p0 * p1);
    }
    for (int j = pro + (nv << 2) + tid; j < len; j += TPB)
        acc += softplus_f(cp[j]);

    // Block reduce acc -> partial softplus sum for this half (in thread 0).
    #pragma unroll
    for (int o = 16; o > 0; o >>= 1)
        acc += __shfl_down_sync(0xFFFFFFFFu, acc, o);
    if (lane == 0) s_warp[wid] = acc;
    __syncthreads();
    if (wid == 0) {
        float v = (lane < TPB / 32) ? s_warp[lane] : 0.0f;
        #pragma unroll
        for (int o = 16; o > 0; o >>= 1)
            v += __shfl_down_sync(0xFFFFFFFFu, v, o);
        acc = v;   // thread 0 holds the half-sum
    }

    // Half-0 CTA: label terms (warp 0), published to globals by thread 0.
    if (half == 0 && wid == 0) {
        float pos = 0.0f, corr = 0.0f;
        int   nfirst = 0;
        if (lane < KPOS) {
            const int t = s_t[lane];
            const float x = __ldg(rp + t);
            pos = -softplus_f(-x);                 // log_sigmoid, per occurrence
            bool first = true;
            #pragma unroll
            for (int j = 0; j < KPOS; ++j)
                if (j < lane && s_t[j] == t) first = false;
            if (first) { corr = softplus_f(x); nfirst = 1; }  // dedup'd
        }
        #pragma unroll
        for (int o = 16; o > 0; o >>= 1) {
            pos    += __shfl_down_sync(0xFFFFFFFFu, pos, o);
            corr   += __shfl_down_sync(0xFFFFFFFFu, corr, o);
            nfirst += __shfl_down_sync(0xFFFFFFFFu, nfirst, o);
        }
        if (lane == 0) {
            g_pos[row]    = pos;
            g_corr[row]   = corr;
            g_nfirst[row] = nfirst;
        }
    }

    // Combine halves: 2 atomicAdds per row (commutative -> deterministic).
    // Second arrival finalizes the row; last finalizer reduces all rows.
    if (tid == 0) {
        s_last = 0;
        atomicAdd(&g_row_sum[row], acc);
        __threadfence();                            // sum + label stores visible
        unsigned int oldr = atomicAdd(&g_row_cnt[row], 1u);
        if (oldr == 1u) {                           // both halves done
            const float S    = __ldcg(&g_row_sum[row]);
            const float pos  = __ldcg(&g_pos[row]);
            const float corr = __ldcg(&g_corr[row]);
            const int   nf   = __ldcg(&g_nfirst[row]);
            g_row_loss[row] = pos / (float)KPOS
                            + (corr - S) / (float)(NCLASSES - nf);
            g_row_sum[row] = 0.0f;                  // reset for next replay
            g_row_cnt[row] = 0u;
            __threadfence();
            unsigned int oldg = atomicAdd(&g_done, 1u);
            if (oldg == BATCH - 1u) s_last = 1;
        }
    }
    __syncthreads();

    // Deterministic final reduce over the 2048 row losses in the last CTA.
    if (s_last) {
        float a = 0.0f;
        for (int r = tid; r < BATCH; r += TPB)
            a += __ldcg(&g_row_loss[r]);
        #pragma unroll
        for (int o = 16; o > 0; o >>= 1)
            a += __shfl_down_sync(0xFFFFFFFFu, a, o);
        if (lane == 0) s_warp[wid] = a;
        __syncthreads();
        if (wid == 0) {
            float v = (lane < TPB / 32) ? s_warp[lane] : 0.0f;
            #pragma unroll
            for (int o = 16; o > 0; o >>= 1)
                v += __shfl_down_sync(0xFFFFFFFFu, v, o);
            if (lane == 0) {
                out[0] = -v / (float)BATCH;
                g_done = 0;                         // reset for next replay
            }
        }
    }
}

extern "C" void kernel_launch(void* const* d_in, const int* in_sizes, int n_in,
                              void* d_out, int out_size) {
    const float* inp = (const float*)d_in[0];
    const int*   tgt = (const int*)d_in[1];
    if (n_in >= 2 && in_sizes[0] == BATCH * KPOS && in_sizes[1] == BATCH * NCLASSES) {
        inp = (const float*)d_in[1];
        tgt = (const int*)d_in[0];
    }
    mlsm_half_kernel<<<BATCH * 2, TPB>>>(inp, tgt, (float*)d_out);
}